// round 2
// baseline (speedup 1.0000x reference)
#include <cuda_runtime.h>
#include <math.h>

#define BATCH 4
#define TLEN  2048
#define CDIM  2048
#define HS    64
#define NH    32
#define MTOT  (BATCH*TLEN)   /* 8192 */

/* ---------------- scratch (static device allocations; no cudaMalloc) ------- */
__device__ float g_X  [(size_t)MTOT*CDIM];
__device__ float g_XX1[(size_t)MTOT*128];
__device__ float g_MIX[4][(size_t)MTOT*CDIM];
__device__ float g_XW1[(size_t)MTOT*32];
__device__ float g_MW [(size_t)MTOT*CDIM];
__device__ float g_XW [(size_t)MTOT*CDIM];
__device__ float g_T1 [(size_t)MTOT*128];
__device__ float g_DEC[(size_t)MTOT*CDIM];
__device__ float g_R  [(size_t)MTOT*CDIM];
__device__ float g_K  [(size_t)MTOT*CDIM];
__device__ float g_V  [(size_t)MTOT*CDIM];
__device__ float g_V2 [(size_t)MTOT*CDIM];
__device__ float g_Y  [(size_t)MTOT*CDIM];
__device__ float g_YN [(size_t)MTOT*CDIM];

/* ---------------- packed fp32 FMA (SASS FFMA2; ptxas never emits this) ----- */
__device__ __forceinline__ void fma2(unsigned long long& d,
                                     unsigned long long a,
                                     unsigned long long b)
{
    asm("fma.rn.f32x2 %0, %1, %2, %0;" : "+l"(d) : "l"(a), "l"(b));
}

/* ---------------- big NT SGEMM via FFMA2: C[m,n] = sum_k A[m,k]*B[n,k] -----
   BM=128, BN=256, BK=16, 256 threads, 8x16 microtile (64 FMA2/thread/kk).
   A is stored lane-DUPLICATED in shared (As2[kk][2r]=As2[kk][2r+1]) so the
   FMA2 a-operand pairs load directly as 16B LDS; B pairs are natural along
   n. B columns are XOR-swizzled at 16B-chunk granularity to kill the
   64B-stride bank conflicts of the tx*16 read pattern.                     */
__global__ __launch_bounds__(256, 1)
void gemm_nt256(const float* __restrict__ A, const float* __restrict__ B,
                float* __restrict__ C, int M, int N, int K)
{
    __shared__ float As2[16][256];   /* duplicated A rows                  */
    __shared__ float Bs [16][256];   /* chunk-swizzled B                   */
    const int tid = threadIdx.x;
    const int bm = blockIdx.y * 128;
    const int bn = blockIdx.x * 256;
    const int tx = tid & 15;         /* 16 col-groups of 16                */
    const int ty = tid >> 4;         /* 16 row-groups of 8                 */

    unsigned long long acc[8][8];    /* 8 rows x 8 col-pairs = 8x16 tile   */
#pragma unroll
    for (int r = 0; r < 8; r++)
#pragma unroll
        for (int c = 0; c < 8; c++) acc[r][c] = 0ull;

    /* loader mapping */
    const int ra = tid >> 1, ka = (tid & 1) * 8;        /* A: row, k-offset */
    const int chunkb = tid >> 2;                        /* B store chunk    */
    const int scolb = (((chunkb ^ ((chunkb >> 3) & 7)) & 63) << 2) | (tid & 3);

    /* swizzled read columns for the compute phase */
    int bcol[4];
#pragma unroll
    for (int q = 0; q < 4; q++) {
        int cc = tx * 4 + q;
        bcol[q] = ((cc ^ ((cc >> 3) & 7)) << 2);
    }

    const float* Ap = A + (size_t)(bm + ra) * K + ka;
    const float* Bp = B + (size_t)(bn + tid) * K;

    float4 pa0 = *(const float4*)(Ap + 0);
    float4 pa1 = *(const float4*)(Ap + 4);
    float4 pb0 = *(const float4*)(Bp + 0);
    float4 pb1 = *(const float4*)(Bp + 4);
    float4 pb2 = *(const float4*)(Bp + 8);
    float4 pb3 = *(const float4*)(Bp + 12);

    for (int k0 = 0; k0 < K; k0 += 16) {
        /* store current tile: A duplicated as float2{a,a} (STS.64) */
        {
            float2* d;
            d = (float2*)&As2[ka+0][2*ra]; *d = make_float2(pa0.x, pa0.x);
            d = (float2*)&As2[ka+1][2*ra]; *d = make_float2(pa0.y, pa0.y);
            d = (float2*)&As2[ka+2][2*ra]; *d = make_float2(pa0.z, pa0.z);
            d = (float2*)&As2[ka+3][2*ra]; *d = make_float2(pa0.w, pa0.w);
            d = (float2*)&As2[ka+4][2*ra]; *d = make_float2(pa1.x, pa1.x);
            d = (float2*)&As2[ka+5][2*ra]; *d = make_float2(pa1.y, pa1.y);
            d = (float2*)&As2[ka+6][2*ra]; *d = make_float2(pa1.z, pa1.z);
            d = (float2*)&As2[ka+7][2*ra]; *d = make_float2(pa1.w, pa1.w);
        }
        Bs[ 0][scolb] = pb0.x; Bs[ 1][scolb] = pb0.y;
        Bs[ 2][scolb] = pb0.z; Bs[ 3][scolb] = pb0.w;
        Bs[ 4][scolb] = pb1.x; Bs[ 5][scolb] = pb1.y;
        Bs[ 6][scolb] = pb1.z; Bs[ 7][scolb] = pb1.w;
        Bs[ 8][scolb] = pb2.x; Bs[ 9][scolb] = pb2.y;
        Bs[10][scolb] = pb2.z; Bs[11][scolb] = pb2.w;
        Bs[12][scolb] = pb3.x; Bs[13][scolb] = pb3.y;
        Bs[14][scolb] = pb3.z; Bs[15][scolb] = pb3.w;
        __syncthreads();

        if (k0 + 16 < K) {
            const float* An = Ap + k0 + 16;
            const float* Bn = Bp + k0 + 16;
            pa0 = *(const float4*)(An + 0);
            pa1 = *(const float4*)(An + 4);
            pb0 = *(const float4*)(Bn + 0);
            pb1 = *(const float4*)(Bn + 4);
            pb2 = *(const float4*)(Bn + 8);
            pb3 = *(const float4*)(Bn + 12);
        }

#pragma unroll
        for (int kk = 0; kk < 16; kk++) {
            unsigned long long a2[8], b2[8];
            {
                const ulonglong2* ap = (const ulonglong2*)&As2[kk][ty * 16];
                ulonglong2 t0 = ap[0], t1 = ap[1], t2 = ap[2], t3 = ap[3];
                a2[0] = t0.x; a2[1] = t0.y; a2[2] = t1.x; a2[3] = t1.y;
                a2[4] = t2.x; a2[5] = t2.y; a2[6] = t3.x; a2[7] = t3.y;
            }
#pragma unroll
            for (int q = 0; q < 4; q++) {
                ulonglong2 bq = *(const ulonglong2*)&Bs[kk][bcol[q]];
                b2[2*q]   = bq.x;
                b2[2*q+1] = bq.y;
            }
#pragma unroll
            for (int r = 0; r < 8; r++)
#pragma unroll
                for (int c = 0; c < 8; c++)
                    fma2(acc[r][c], a2[r], b2[c]);
        }
        __syncthreads();
    }

    /* epilogue: acc[r][2q],[2q+1] cover logical cols tx*16 + q*4 + 0..3 */
#pragma unroll
    for (int r = 0; r < 8; r++) {
        float* crow = &C[(size_t)(bm + ty * 8 + r) * N + bn + tx * 16];
#pragma unroll
        for (int q = 0; q < 4; q++) {
            ulonglong2 v;
            v.x = acc[r][2*q];
            v.y = acc[r][2*q+1];
            *(ulonglong2*)&crow[q * 4] = v;
        }
    }
}

/* ---------------- generic NN GEMM: C[m,n] = f(sum_k A[m,lda..]*B[k,n]) ------
   BM=64, BN=128, BK=32. epi: 0=none, 1=tanh, 2=exp(-exp(bias[n]+acc)).    */
__global__ __launch_bounds__(256, 2)
void gemm_nn(const float* __restrict__ A, int lda, int aoff,
             const float* __restrict__ B, int ldb,
             float* __restrict__ C, int ldc,
             int M, int N, int K, int epi, const float* __restrict__ bias)
{
    __shared__ float As[64][36];
    __shared__ float Bs[32][128];
    const int tid = threadIdx.x;
    const int bm = blockIdx.y * 64;
    const int bn = blockIdx.x * 128;
    const int cx = tid & 31;
    const int rg = tid >> 5;

    float4 acc[8];
#pragma unroll
    for (int r = 0; r < 8; r++) acc[r] = make_float4(0.f,0.f,0.f,0.f);

    for (int k0 = 0; k0 < K; k0 += 32) {
#pragma unroll
        for (int u = 0; u < 2; u++) {
            int i = tid + 256*u;
            int r = i >> 3, kq = (i & 7) << 2;
            float4 v = *(const float4*)&A[(size_t)(bm + r) * lda + aoff + k0 + kq];
            *(float4*)&As[r][kq] = v;
        }
#pragma unroll
        for (int u = 0; u < 4; u++) {
            int i = tid + 256*u;
            int kr = i >> 5, nq = (i & 31) << 2;
            float4 v = make_float4(0.f,0.f,0.f,0.f);
            if (bn + nq < N)
                v = *(const float4*)&B[(size_t)(k0 + kr) * ldb + bn + nq];
            *(float4*)&Bs[kr][nq] = v;
        }
        __syncthreads();
#pragma unroll 8
        for (int k = 0; k < 32; k++) {
            float4 bv = *(const float4*)&Bs[k][cx << 2];
#pragma unroll
            for (int r = 0; r < 8; r++) {
                float a = As[rg*8 + r][k];
                acc[r].x = fmaf(a, bv.x, acc[r].x);
                acc[r].y = fmaf(a, bv.y, acc[r].y);
                acc[r].z = fmaf(a, bv.z, acc[r].z);
                acc[r].w = fmaf(a, bv.w, acc[r].w);
            }
        }
        __syncthreads();
    }
    const int n = bn + (cx << 2);
    if (n < N) {
#pragma unroll
        for (int r = 0; r < 8; r++) {
            float4 o = acc[r];
            if (epi == 1) {
                o.x = tanhf(o.x); o.y = tanhf(o.y); o.z = tanhf(o.z); o.w = tanhf(o.w);
            } else if (epi == 2) {
                o.x = expf(-expf(bias[n+0] + o.x));
                o.y = expf(-expf(bias[n+1] + o.y));
                o.z = expf(-expf(bias[n+2] + o.z));
                o.w = expf(-expf(bias[n+3] + o.w));
            }
            *(float4*)&C[(size_t)(bm + rg*8 + r) * ldc + n] = o;
        }
    }
}

/* ---------------- elementwise: XW = x + dxprev*(time_maa_w + mw) ----------- */
__global__ void ew_xw_kernel(const float* __restrict__ X, const float* __restrict__ shiftst,
                             const float* __restrict__ MW, const float* __restrict__ tmw,
                             float* __restrict__ XW)
{
    int i4 = blockIdx.x * 256 + threadIdx.x;          /* over MTOT*CDIM/4 */
    int m = i4 >> 9, c4 = i4 & 511;
    int t = m & (TLEN-1), b = m >> 11;
    const float4* X4 = (const float4*)X;
    float4 x  = X4[i4];
    float4 xp = (t == 0) ? ((const float4*)shiftst)[(b << 9) + c4] : X4[i4 - 512];
    float4 mw = ((const float4*)MW)[i4];
    float4 w  = ((const float4*)tmw)[c4];
    float4 o;
    o.x = x.x + (xp.x - x.x) * (w.x + mw.x);
    o.y = x.y + (xp.y - x.y) * (w.y + mw.y);
    o.z = x.z + (xp.z - x.z) * (w.z + mw.z);
    o.w = x.w + (xp.w - x.w) * (w.w + mw.w);
    ((float4*)XW)[i4] = o;
}

/* ---------------- elementwise: r, k, v, v2 --------------------------------- */
__global__ void ew_rkvv_kernel(const float* __restrict__ X, const float* __restrict__ shiftst,
    const float* __restrict__ M0, const float* __restrict__ M1,
    const float* __restrict__ M2, const float* __restrict__ M3,
    const float* __restrict__ DEC,
    const float* __restrict__ tmr, const float* __restrict__ tmk,
    const float* __restrict__ tmv, const float* __restrict__ tmv2,
    const float* __restrict__ trec, const float* __restrict__ tkey,
    float* __restrict__ R, float* __restrict__ K,
    float* __restrict__ V, float* __restrict__ V2)
{
    int i4 = blockIdx.x * 256 + threadIdx.x;
    int m = i4 >> 9, c4 = i4 & 511;
    int t = m & (TLEN-1), b = m >> 11;
    const float4* X4 = (const float4*)X;
    float4 x  = X4[i4];
    float4 xp = (t == 0) ? ((const float4*)shiftst)[(b << 9) + c4] : X4[i4 - 512];
    float4 m0 = ((const float4*)M0)[i4];
    float4 m1 = ((const float4*)M1)[i4];
    float4 m2 = ((const float4*)M2)[i4];
    float4 m3 = ((const float4*)M3)[i4];
    float4 d  = ((const float4*)DEC)[i4];
    float4 cr = ((const float4*)tmr)[c4];
    float4 ck = ((const float4*)tmk)[c4];
    float4 cv = ((const float4*)tmv)[c4];
    float4 c2 = ((const float4*)tmv2)[c4];
    float4 rc = ((const float4*)trec)[c4];
    float4 kc = ((const float4*)tkey)[c4];
    float4 o_r, o_k, o_v, o_w;
#define RKVV_APPLY(f) do { \
    float dxv = xp.f - x.f; \
    o_r.f = (x.f + dxv*(cr.f + m0.f)) * rc.f; \
    o_k.f = (x.f + dxv*(ck.f + m1.f)) * kc.f * (1.f - d.f); \
    o_v.f =  x.f + dxv*(cv.f + m2.f); \
    o_w.f =  x.f + dxv*(c2.f + m3.f); \
} while(0)
    RKVV_APPLY(x); RKVV_APPLY(y); RKVV_APPLY(z); RKVV_APPLY(w);
#undef RKVV_APPLY
    ((float4*)R )[i4] = o_r;
    ((float4*)K )[i4] = o_k;
    ((float4*)V )[i4] = o_v;
    ((float4*)V2)[i4] = o_w;
}

/* ---------------- WKV sequential scan -------------------------------------- */
__global__ __launch_bounds__(256, 1)
void wkv_kernel(const float* __restrict__ Rp, const float* __restrict__ Kp,
                const float* __restrict__ Vp, const float* __restrict__ Dp,
                const float* __restrict__ S0, float* __restrict__ Y)
{
    const int bh = blockIdx.x;
    const int b = bh >> 5, h = bh & (NH-1);
    const int tid = threadIdx.x;
    const int j = tid >> 2, iq = tid & 3, i0 = iq << 4;

    float S[16];
    const float* s0p = S0 + (size_t)bh * HS * HS;
#pragma unroll
    for (int ii = 0; ii < 16; ii++) S[ii] = s0p[(i0 + ii) * HS + j];

    __shared__ float sbuf[2][4][64];     /* [buf][r,k,d,v][i or j] */

    const int grp = tid >> 6, lane = tid & 63;
    const size_t base = ((size_t)b * TLEN) * CDIM + h * HS;
    const float* myp =
        ((grp == 0) ? Rp : (grp == 1) ? Kp : (grp == 2) ? Dp : Vp) + base + lane;

    float pre[4];
#pragma unroll
    for (int u = 0; u < 4; u++) pre[u] = myp[(size_t)u * CDIM];

    const size_t ybase = base;
    for (int tc = 0; tc < TLEN; tc += 4) {
        float cur[4];
#pragma unroll
        for (int u = 0; u < 4; u++) cur[u] = pre[u];
        if (tc + 4 < TLEN) {
#pragma unroll
            for (int u = 0; u < 4; u++) pre[u] = myp[(size_t)(tc + 4 + u) * CDIM];
        }
#pragma unroll
        for (int u = 0; u < 4; u++) {
            const int t = tc + u;
            const int buf = t & 1;
            sbuf[buf][grp][lane] = cur[u];
            __syncthreads();
            const float4* r4 = (const float4*)sbuf[buf][0];
            const float4* k4 = (const float4*)sbuf[buf][1];
            const float4* d4 = (const float4*)sbuf[buf][2];
            const float vj = sbuf[buf][3][j];
            float y = 0.f;
#pragma unroll
            for (int q = 0; q < 4; q++) {
                float4 rv = r4[iq*4 + q];
                y = fmaf(rv.x, S[q*4+0], y);
                y = fmaf(rv.y, S[q*4+1], y);
                y = fmaf(rv.z, S[q*4+2], y);
                y = fmaf(rv.w, S[q*4+3], y);
            }
#pragma unroll
            for (int q = 0; q < 4; q++) {
                float4 dv = d4[iq*4 + q];
                float4 kv = k4[iq*4 + q];
                S[q*4+0] = fmaf(dv.x, S[q*4+0], kv.x * vj);
                S[q*4+1] = fmaf(dv.y, S[q*4+1], kv.y * vj);
                S[q*4+2] = fmaf(dv.z, S[q*4+2], kv.z * vj);
                S[q*4+3] = fmaf(dv.w, S[q*4+3], kv.w * vj);
            }
            y += __shfl_xor_sync(0xffffffffu, y, 1);
            y += __shfl_xor_sync(0xffffffffu, y, 2);
            if (iq == 0) Y[ybase + (size_t)t * CDIM + j] = y;
        }
    }
}

/* ---------------- fused add + LayerNorm ------------------------------------ */
__global__ void ln_kernel(const float* __restrict__ Y, const float* __restrict__ V2,
                          const float* __restrict__ gamma, const float* __restrict__ beta,
                          float* __restrict__ YN)
{
    const int m = blockIdx.x;
    const int tid = threadIdx.x;
    const float4* y4 = (const float4*)(Y  + (size_t)m * CDIM);
    const float4* v4 = (const float4*)(V2 + (size_t)m * CDIM);
    float4 vals[2];
    float s = 0.f, s2 = 0.f;
#pragma unroll
    for (int u = 0; u < 2; u++) {
        float4 a = y4[tid + u*256], b = v4[tid + u*256];
        float4 v = make_float4(a.x+b.x, a.y+b.y, a.z+b.z, a.w+b.w);
        vals[u] = v;
        s  += v.x + v.y + v.z + v.w;
        s2 += v.x*v.x + v.y*v.y + v.z*v.z + v.w*v.w;
    }
#pragma unroll
    for (int o = 16; o; o >>= 1) {
        s  += __shfl_xor_sync(0xffffffffu, s,  o);
        s2 += __shfl_xor_sync(0xffffffffu, s2, o);
    }
    __shared__ float sh[2][8];
    const int w = tid >> 5, l = tid & 31;
    if (l == 0) { sh[0][w] = s; sh[1][w] = s2; }
    __syncthreads();
    s = 0.f; s2 = 0.f;
#pragma unroll
    for (int i = 0; i < 8; i++) { s += sh[0][i]; s2 += sh[1][i]; }
    const float mu   = s  * (1.f / CDIM);
    const float var  = s2 * (1.f / CDIM) - mu * mu;
    const float rstd = rsqrtf(var + 1e-5f);
    const float4* g4 = (const float4*)gamma;
    const float4* b4 = (const float4*)beta;
    float4* o4 = (float4*)(YN + (size_t)m * CDIM);
#pragma unroll
    for (int u = 0; u < 2; u++) {
        int c4 = tid + u*256;
        float4 g = g4[c4], bb = b4[c4], v = vals[u];
        float4 o;
        o.x = (v.x - mu) * rstd * g.x + bb.x;
        o.y = (v.y - mu) * rstd * g.y + bb.y;
        o.z = (v.z - mu) * rstd * g.z + bb.z;
        o.w = (v.w - mu) * rstd * g.w + bb.w;
        o4[c4] = o;
    }
}

/* ---------------- launch --------------------------------------------------- */
extern "C" void kernel_launch(void* const* d_in, const int* in_sizes, int n_in,
                              void* d_out, int out_size)
{
    const float* x_in     = (const float*)d_in[0];
    const float* shiftst  = (const float*)d_in[1];
    const float* wkvstate = (const float*)d_in[2];
    const float* tmr      = (const float*)d_in[3];
    const float* tmk      = (const float*)d_in[4];
    const float* tmv      = (const float*)d_in[5];
    const float* tmv2     = (const float*)d_in[6];
    const float* maa_w1   = (const float*)d_in[7];
    const float* maa_w2   = (const float*)d_in[8];
    const float* tmw      = (const float*)d_in[9];
    const float* ww1      = (const float*)d_in[10];
    const float* ww2      = (const float*)d_in[11];
    const float* tdecay   = (const float*)d_in[12];
    const float* dw1      = (const float*)d_in[13];
    const float* dw2      = (const float*)d_in[14];
    /* d_in[15] = time_faaaa: unused (u == 0 in this model) */
    const float* trec     = (const float*)d_in[16];
    const float* tkey     = (const float*)d_in[17];
    const float* value_w  = (const float*)d_in[18];
    const float* output_w = (const float*)d_in[19];
    const float* gamma    = (const float*)d_in[20];
    const float* beta     = (const float*)d_in[21];
    float* out = (float*)d_out;

    float *pX, *pXX1, *pMIX, *pXW1, *pMW, *pXW, *pT1, *pDEC, *pR, *pK, *pV, *pV2, *pY, *pYN;
    cudaGetSymbolAddress((void**)&pX,   g_X);
    cudaGetSymbolAddress((void**)&pXX1, g_XX1);
    cudaGetSymbolAddress((void**)&pMIX, g_MIX);
    cudaGetSymbolAddress((void**)&pXW1, g_XW1);
    cudaGetSymbolAddress((void**)&pMW,  g_MW);
    cudaGetSymbolAddress((void**)&pXW,  g_XW);
    cudaGetSymbolAddress((void**)&pT1,  g_T1);
    cudaGetSymbolAddress((void**)&pDEC, g_DEC);
    cudaGetSymbolAddress((void**)&pR,   g_R);
    cudaGetSymbolAddress((void**)&pK,   g_K);
    cudaGetSymbolAddress((void**)&pV,   g_V);
    cudaGetSymbolAddress((void**)&pV2,  g_V2);
    cudaGetSymbolAddress((void**)&pY,   g_Y);
    cudaGetSymbolAddress((void**)&pYN,  g_YN);

    const size_t SZ = (size_t)MTOT * CDIM;
    const int EW_BLOCKS = (int)(SZ / 4 / 256);

    /* X = x_in @ value_w^T  (FFMA2 path) */
    gemm_nt256<<<dim3(CDIM/256, MTOT/128), 256>>>(x_in, value_w, pX, MTOT, CDIM, CDIM);
    /* XX1 = tanh(x_in @ maa_w1) */
    gemm_nn<<<dim3(1, MTOT/64), 256>>>(x_in, CDIM, 0, maa_w1, 128, pXX1, 128,
                                       MTOT, 128, CDIM, 1, (const float*)0);
    /* MIX[f] = XX1[:, f*32:(f+1)*32] @ maa_w2[f] */
    for (int f = 0; f < 4; f++)
        gemm_nn<<<dim3(CDIM/128, MTOT/64), 256>>>(pXX1, 128, f*32,
                                                  maa_w2 + (size_t)f*32*CDIM, CDIM,
                                                  pMIX + (size_t)f*SZ, CDIM,
                                                  MTOT, CDIM, 32, 0, (const float*)0);
    /* XW1 = tanh(X @ w_w1) */
    gemm_nn<<<dim3(1, MTOT/64), 256>>>(pX, CDIM, 0, ww1, 32, pXW1, 32,
                                       MTOT, 32, CDIM, 1, (const float*)0);
    /* MW = XW1 @ w_w2 */
    gemm_nn<<<dim3(CDIM/128, MTOT/64), 256>>>(pXW1, 32, 0, ww2, CDIM, pMW, CDIM,
                                              MTOT, CDIM, 32, 0, (const float*)0);
    /* XW = X + dxprev*(time_maa_w + MW) */
    ew_xw_kernel<<<EW_BLOCKS, 256>>>(pX, shiftst, pMW, tmw, pXW);
    /* T1 = tanh(XW @ decay_w1) */
    gemm_nn<<<dim3(1, MTOT/64), 256>>>(pXW, CDIM, 0, dw1, 128, pT1, 128,
                                       MTOT, 128, CDIM, 1, (const float*)0);
    /* DEC = exp(-exp(time_decay + T1 @ decay_w2)) */
    gemm_nn<<<dim3(CDIM/128, MTOT/64), 256>>>(pT1, 128, 0, dw2, CDIM, pDEC, CDIM,
                                              MTOT, CDIM, 128, 2, tdecay);
    /* r, k, v, v2 */
    ew_rkvv_kernel<<<EW_BLOCKS, 256>>>(pX, shiftst,
                                       pMIX, pMIX + SZ, pMIX + 2*SZ, pMIX + 3*SZ,
                                       pDEC, tmr, tmk, tmv, tmv2, trec, tkey,
                                       pR, pK, pV, pV2);
    /* WKV scan */
    wkv_kernel<<<BATCH*NH, 256>>>(pR, pK, pV, pDEC, wkvstate, pY);
    /* yn = LN(y + v2) */
    ln_kernel<<<MTOT, 256>>>(pY, pV2, gamma, beta, pYN);
    /* out = yn @ output_w^T  (FFMA2 path) */
    gemm_nt256<<<dim3(CDIM/256, MTOT/128), 256>>>(pYN, output_w, out, MTOT, CDIM, CDIM);
}

// round 6
// speedup vs baseline: 1.4296x; 1.4296x over previous
#include <cuda_runtime.h>
#include <cuda_bf16.h>
#include <mma.h>
#include <math.h>
#include <stdint.h>

using namespace nvcuda;

#define BATCH 4
#define TLEN  2048
#define CDIM  2048
#define HS    64
#define NH    32
#define MTOT  (BATCH*TLEN)   /* 8192 */

/* ---------------- scratch (static device allocations; no cudaMalloc) ------- */
__device__ float g_X  [(size_t)MTOT*CDIM];
__device__ float g_XX1[(size_t)MTOT*128];
__device__ float g_MIX[4][(size_t)MTOT*CDIM];
__device__ float g_XW1[(size_t)MTOT*32];
__device__ float g_MW [(size_t)MTOT*CDIM];
__device__ float g_XW [(size_t)MTOT*CDIM];
__device__ float g_T1 [(size_t)MTOT*128];
__device__ float g_DEC[(size_t)MTOT*CDIM];
__device__ float g_R  [(size_t)MTOT*CDIM];
__device__ float g_K  [(size_t)MTOT*CDIM];
__device__ float g_V  [(size_t)MTOT*CDIM];
__device__ float g_V2 [(size_t)MTOT*CDIM];
__device__ float g_Y  [(size_t)MTOT*CDIM];
/* bf16 hi/lo splits */
__device__ __nv_bfloat16 g_XIH[(size_t)MTOT*CDIM];
__device__ __nv_bfloat16 g_XIL[(size_t)MTOT*CDIM];
__device__ __nv_bfloat16 g_YH [(size_t)MTOT*CDIM];
__device__ __nv_bfloat16 g_YL [(size_t)MTOT*CDIM];
__device__ __nv_bfloat16 g_VWH[(size_t)CDIM*CDIM];
__device__ __nv_bfloat16 g_VWL[(size_t)CDIM*CDIM];
__device__ __nv_bfloat16 g_OWH[(size_t)CDIM*CDIM];
__device__ __nv_bfloat16 g_OWL[(size_t)CDIM*CDIM];

/* ================= bf16-split WMMA GEMM (NT) =================
   C[m,n] = sum_k A[m,k]*B[n,k],  A = AH+AL, B = BH+BL (bf16 hi/lo).
   Accumulate AH*BH + AH*BL + AL*BH in fp32 (lo*lo term dropped).
   Block 128x128, 8 warps (2 x 4), warp tile 64x32, K-chunk 32.      */
#define WLD 40   /* smem row pitch in bf16 (128B-ish, conflict-softening pad) */

__global__ __launch_bounds__(256)
void gemm_wmma3(const __nv_bfloat16* __restrict__ AH, const __nv_bfloat16* __restrict__ AL,
                const __nv_bfloat16* __restrict__ BH, const __nv_bfloat16* __restrict__ BL,
                float* __restrict__ C, int M, int N, int K)
{
    __shared__ __nv_bfloat16 AsH[128][WLD];
    __shared__ __nv_bfloat16 AsL[128][WLD];
    __shared__ __nv_bfloat16 BsH[128][WLD];
    __shared__ __nv_bfloat16 BsL[128][WLD];

    const int tid = threadIdx.x;
    const int wid = tid >> 5;
    const int wm = wid & 1;        /* 0..1  -> 64-row slab  */
    const int wn = wid >> 1;       /* 0..3  -> 32-col slab  */
    const int bm = blockIdx.y * 128;
    const int bn = blockIdx.x * 128;

    wmma::fragment<wmma::accumulator, 16, 16, 16, float> acc[4][2];
#pragma unroll
    for (int i = 0; i < 4; i++)
#pragma unroll
        for (int j = 0; j < 2; j++) wmma::fill_fragment(acc[i][j], 0.f);

    for (int k0 = 0; k0 < K; k0 += 32) {
#pragma unroll
        for (int u = 0; u < 2; u++) {
            int i = tid + (u << 8);              /* 0..511 */
            int row = i >> 2, c8 = (i & 3) << 3; /* 8 bf16 per uint4 */
            size_t sa = (size_t)(bm + row) * K + k0 + c8;
            size_t sb = (size_t)(bn + row) * K + k0 + c8;
            *(uint4*)&AsH[row][c8] = *(const uint4*)(AH + sa);
            *(uint4*)&AsL[row][c8] = *(const uint4*)(AL + sa);
            *(uint4*)&BsH[row][c8] = *(const uint4*)(BH + sb);
            *(uint4*)&BsL[row][c8] = *(const uint4*)(BL + sb);
        }
        __syncthreads();

#pragma unroll
        for (int ks = 0; ks < 2; ks++) {
            wmma::fragment<wmma::matrix_b, 16, 16, 16, __nv_bfloat16, wmma::col_major> bh[2], bl[2];
#pragma unroll
            for (int j = 0; j < 2; j++) {
                wmma::load_matrix_sync(bh[j], &BsH[wn*32 + j*16][ks*16], WLD);
                wmma::load_matrix_sync(bl[j], &BsL[wn*32 + j*16][ks*16], WLD);
            }
#pragma unroll
            for (int i = 0; i < 4; i++) {
                wmma::fragment<wmma::matrix_a, 16, 16, 16, __nv_bfloat16, wmma::row_major> ah, al;
                wmma::load_matrix_sync(ah, &AsH[wm*64 + i*16][ks*16], WLD);
                wmma::load_matrix_sync(al, &AsL[wm*64 + i*16][ks*16], WLD);
#pragma unroll
                for (int j = 0; j < 2; j++) {
                    wmma::mma_sync(acc[i][j], ah, bh[j], acc[i][j]);
                    wmma::mma_sync(acc[i][j], ah, bl[j], acc[i][j]);
                    wmma::mma_sync(acc[i][j], al, bh[j], acc[i][j]);
                }
            }
        }
        __syncthreads();
    }

#pragma unroll
    for (int i = 0; i < 4; i++)
#pragma unroll
        for (int j = 0; j < 2; j++)
            wmma::store_matrix_sync(&C[(size_t)(bm + wm*64 + i*16) * N + bn + wn*32 + j*16],
                                    acc[i][j], N, wmma::mem_row_major);
}

/* ---------------- fp32 -> bf16 hi/lo split --------------------------------- */
__global__ void split_kernel(const float* __restrict__ in,
                             __nv_bfloat16* __restrict__ hi,
                             __nv_bfloat16* __restrict__ lo, int n4)
{
    int i = blockIdx.x * 256 + threadIdx.x;
    if (i >= n4) return;
    float4 x = ((const float4*)in)[i];
    __nv_bfloat16 h0 = __float2bfloat16(x.x), h1 = __float2bfloat16(x.y);
    __nv_bfloat16 h2 = __float2bfloat16(x.z), h3 = __float2bfloat16(x.w);
    __nv_bfloat162 hA; hA.x = h0; hA.y = h1;
    __nv_bfloat162 hB; hB.x = h2; hB.y = h3;
    __nv_bfloat162 lA; lA.x = __float2bfloat16(x.x - __bfloat162float(h0));
                       lA.y = __float2bfloat16(x.y - __bfloat162float(h1));
    __nv_bfloat162 lB; lB.x = __float2bfloat16(x.z - __bfloat162float(h2));
                       lB.y = __float2bfloat16(x.w - __bfloat162float(h3));
    ((__nv_bfloat162*)hi)[2*i]   = hA;
    ((__nv_bfloat162*)hi)[2*i+1] = hB;
    ((__nv_bfloat162*)lo)[2*i]   = lA;
    ((__nv_bfloat162*)lo)[2*i+1] = lB;
}

/* ---------------- generic NN GEMM: C[m,n] = f(sum_k A[m,lda..]*B[k,n]) ------ */
__global__ __launch_bounds__(256, 2)
void gemm_nn(const float* __restrict__ A, int lda, int aoff,
             const float* __restrict__ B, int ldb,
             float* __restrict__ C, int ldc,
             int M, int N, int K, int epi, const float* __restrict__ bias)
{
    __shared__ float As[64][36];
    __shared__ float Bs[32][128];
    const int tid = threadIdx.x;
    const int bm = blockIdx.y * 64;
    const int bn = blockIdx.x * 128;
    const int cx = tid & 31;
    const int rg = tid >> 5;

    float4 acc[8];
#pragma unroll
    for (int r = 0; r < 8; r++) acc[r] = make_float4(0.f,0.f,0.f,0.f);

    for (int k0 = 0; k0 < K; k0 += 32) {
#pragma unroll
        for (int u = 0; u < 2; u++) {
            int i = tid + 256*u;
            int r = i >> 3, kq = (i & 7) << 2;
            float4 v = *(const float4*)&A[(size_t)(bm + r) * lda + aoff + k0 + kq];
            *(float4*)&As[r][kq] = v;
        }
#pragma unroll
        for (int u = 0; u < 4; u++) {
            int i = tid + 256*u;
            int kr = i >> 5, nq = (i & 31) << 2;
            float4 v = make_float4(0.f,0.f,0.f,0.f);
            if (bn + nq < N)
                v = *(const float4*)&B[(size_t)(k0 + kr) * ldb + bn + nq];
            *(float4*)&Bs[kr][nq] = v;
        }
        __syncthreads();
#pragma unroll 8
        for (int k = 0; k < 32; k++) {
            float4 bv = *(const float4*)&Bs[k][cx << 2];
#pragma unroll
            for (int r = 0; r < 8; r++) {
                float a = As[rg*8 + r][k];
                acc[r].x = fmaf(a, bv.x, acc[r].x);
                acc[r].y = fmaf(a, bv.y, acc[r].y);
                acc[r].z = fmaf(a, bv.z, acc[r].z);
                acc[r].w = fmaf(a, bv.w, acc[r].w);
            }
        }
        __syncthreads();
    }
    const int n = bn + (cx << 2);
    if (n < N) {
#pragma unroll
        for (int r = 0; r < 8; r++) {
            float4 o = acc[r];
            if (epi == 1) {
                o.x = tanhf(o.x); o.y = tanhf(o.y); o.z = tanhf(o.z); o.w = tanhf(o.w);
            } else if (epi == 2) {
                o.x = expf(-expf(bias[n+0] + o.x));
                o.y = expf(-expf(bias[n+1] + o.y));
                o.z = expf(-expf(bias[n+2] + o.z));
                o.w = expf(-expf(bias[n+3] + o.w));
            }
            *(float4*)&C[(size_t)(bm + rg*8 + r) * ldc + n] = o;
        }
    }
}

/* ---------------- elementwise: XW = x + dxprev*(time_maa_w + mw) ----------- */
__global__ void ew_xw_kernel(const float* __restrict__ X, const float* __restrict__ shiftst,
                             const float* __restrict__ MW, const float* __restrict__ tmw,
                             float* __restrict__ XW)
{
    int i4 = blockIdx.x * 256 + threadIdx.x;
    int m = i4 >> 9, c4 = i4 & 511;
    int t = m & (TLEN-1), b = m >> 11;
    const float4* X4 = (const float4*)X;
    float4 x  = X4[i4];
    float4 xp = (t == 0) ? ((const float4*)shiftst)[(b << 9) + c4] : X4[i4 - 512];
    float4 mw = ((const float4*)MW)[i4];
    float4 w  = ((const float4*)tmw)[c4];
    float4 o;
    o.x = x.x + (xp.x - x.x) * (w.x + mw.x);
    o.y = x.y + (xp.y - x.y) * (w.y + mw.y);
    o.z = x.z + (xp.z - x.z) * (w.z + mw.z);
    o.w = x.w + (xp.w - x.w) * (w.w + mw.w);
    ((float4*)XW)[i4] = o;
}

/* ---------------- elementwise: r, k, v, v2 --------------------------------- */
__global__ void ew_rkvv_kernel(const float* __restrict__ X, const float* __restrict__ shiftst,
    const float* __restrict__ M0, const float* __restrict__ M1,
    const float* __restrict__ M2, const float* __restrict__ M3,
    const float* __restrict__ DEC,
    const float* __restrict__ tmr, const float* __restrict__ tmk,
    const float* __restrict__ tmv, const float* __restrict__ tmv2,
    const float* __restrict__ trec, const float* __restrict__ tkey,
    float* __restrict__ R, float* __restrict__ K,
    float* __restrict__ V, float* __restrict__ V2)
{
    int i4 = blockIdx.x * 256 + threadIdx.x;
    int m = i4 >> 9, c4 = i4 & 511;
    int t = m & (TLEN-1), b = m >> 11;
    const float4* X4 = (const float4*)X;
    float4 x  = X4[i4];
    float4 xp = (t == 0) ? ((const float4*)shiftst)[(b << 9) + c4] : X4[i4 - 512];
    float4 m0 = ((const float4*)M0)[i4];
    float4 m1 = ((const float4*)M1)[i4];
    float4 m2 = ((const float4*)M2)[i4];
    float4 m3 = ((const float4*)M3)[i4];
    float4 d  = ((const float4*)DEC)[i4];
    float4 cr = ((const float4*)tmr)[c4];
    float4 ck = ((const float4*)tmk)[c4];
    float4 cv = ((const float4*)tmv)[c4];
    float4 c2 = ((const float4*)tmv2)[c4];
    float4 rc = ((const float4*)trec)[c4];
    float4 kc = ((const float4*)tkey)[c4];
    float4 o_r, o_k, o_v, o_w;
#define RKVV_APPLY(f) do { \
    float dxv = xp.f - x.f; \
    o_r.f = (x.f + dxv*(cr.f + m0.f)) * rc.f; \
    o_k.f = (x.f + dxv*(ck.f + m1.f)) * kc.f * (1.f - d.f); \
    o_v.f =  x.f + dxv*(cv.f + m2.f); \
    o_w.f =  x.f + dxv*(c2.f + m3.f); \
} while(0)
    RKVV_APPLY(x); RKVV_APPLY(y); RKVV_APPLY(z); RKVV_APPLY(w);
#undef RKVV_APPLY
    ((float4*)R )[i4] = o_r;
    ((float4*)K )[i4] = o_k;
    ((float4*)V )[i4] = o_v;
    ((float4*)V2)[i4] = o_w;
}

/* ---------------- WKV sequential scan -------------------------------------- */
__global__ __launch_bounds__(256, 1)
void wkv_kernel(const float* __restrict__ Rp, const float* __restrict__ Kp,
                const float* __restrict__ Vp, const float* __restrict__ Dp,
                const float* __restrict__ S0, float* __restrict__ Y)
{
    const int bh = blockIdx.x;
    const int b = bh >> 5, h = bh & (NH-1);
    const int tid = threadIdx.x;
    const int j = tid >> 2, iq = tid & 3, i0 = iq << 4;

    float S[16];
    const float* s0p = S0 + (size_t)bh * HS * HS;
#pragma unroll
    for (int ii = 0; ii < 16; ii++) S[ii] = s0p[(i0 + ii) * HS + j];

    __shared__ float sbuf[2][4][64];

    const int grp = tid >> 6, lane = tid & 63;
    const size_t base = ((size_t)b * TLEN) * CDIM + h * HS;
    const float* myp =
        ((grp == 0) ? Rp : (grp == 1) ? Kp : (grp == 2) ? Dp : Vp) + base + lane;

    float pre[4];
#pragma unroll
    for (int u = 0; u < 4; u++) pre[u] = myp[(size_t)u * CDIM];

    const size_t ybase = base;
    for (int tc = 0; tc < TLEN; tc += 4) {
        float cur[4];
#pragma unroll
        for (int u = 0; u < 4; u++) cur[u] = pre[u];
        if (tc + 4 < TLEN) {
#pragma unroll
            for (int u = 0; u < 4; u++) pre[u] = myp[(size_t)(tc + 4 + u) * CDIM];
        }
#pragma unroll
        for (int u = 0; u < 4; u++) {
            const int t = tc + u;
            const int buf = t & 1;
            sbuf[buf][grp][lane] = cur[u];
            __syncthreads();
            const float4* r4 = (const float4*)sbuf[buf][0];
            const float4* k4 = (const float4*)sbuf[buf][1];
            const float4* d4 = (const float4*)sbuf[buf][2];
            const float vj = sbuf[buf][3][j];
            float y = 0.f;
#pragma unroll
            for (int q = 0; q < 4; q++) {
                float4 rv = r4[iq*4 + q];
                y = fmaf(rv.x, S[q*4+0], y);
                y = fmaf(rv.y, S[q*4+1], y);
                y = fmaf(rv.z, S[q*4+2], y);
                y = fmaf(rv.w, S[q*4+3], y);
            }
#pragma unroll
            for (int q = 0; q < 4; q++) {
                float4 dv = d4[iq*4 + q];
                float4 kv = k4[iq*4 + q];
                S[q*4+0] = fmaf(dv.x, S[q*4+0], kv.x * vj);
                S[q*4+1] = fmaf(dv.y, S[q*4+1], kv.y * vj);
                S[q*4+2] = fmaf(dv.z, S[q*4+2], kv.z * vj);
                S[q*4+3] = fmaf(dv.w, S[q*4+3], kv.w * vj);
            }
            y += __shfl_xor_sync(0xffffffffu, y, 1);
            y += __shfl_xor_sync(0xffffffffu, y, 2);
            if (iq == 0) Y[ybase + (size_t)t * CDIM + j] = y;
        }
    }
}

/* ---------------- fused add + LayerNorm -> bf16 hi/lo ---------------------- */
__global__ void ln_kernel(const float* __restrict__ Y, const float* __restrict__ V2,
                          const float* __restrict__ gamma, const float* __restrict__ beta,
                          __nv_bfloat16* __restrict__ YH, __nv_bfloat16* __restrict__ YL)
{
    const int m = blockIdx.x;
    const int tid = threadIdx.x;
    const float4* y4 = (const float4*)(Y  + (size_t)m * CDIM);
    const float4* v4 = (const float4*)(V2 + (size_t)m * CDIM);
    float4 vals[2];
    float s = 0.f, s2 = 0.f;
#pragma unroll
    for (int u = 0; u < 2; u++) {
        float4 a = y4[tid + u*256], b = v4[tid + u*256];
        float4 v = make_float4(a.x+b.x, a.y+b.y, a.z+b.z, a.w+b.w);
        vals[u] = v;
        s  += v.x + v.y + v.z + v.w;
        s2 += v.x*v.x + v.y*v.y + v.z*v.z + v.w*v.w;
    }
#pragma unroll
    for (int o = 16; o; o >>= 1) {
        s  += __shfl_xor_sync(0xffffffffu, s,  o);
        s2 += __shfl_xor_sync(0xffffffffu, s2, o);
    }
    __shared__ float sh[2][8];
    const int w = tid >> 5, l = tid & 31;
    if (l == 0) { sh[0][w] = s; sh[1][w] = s2; }
    __syncthreads();
    s = 0.f; s2 = 0.f;
#pragma unroll
    for (int i = 0; i < 8; i++) { s += sh[0][i]; s2 += sh[1][i]; }
    const float mu   = s  * (1.f / CDIM);
    const float var  = s2 * (1.f / CDIM) - mu * mu;
    const float rstd = rsqrtf(var + 1e-5f);
    const float4* g4 = (const float4*)gamma;
    const float4* b4 = (const float4*)beta;
    __nv_bfloat162* yh2 = (__nv_bfloat162*)(YH + (size_t)m * CDIM);
    __nv_bfloat162* yl2 = (__nv_bfloat162*)(YL + (size_t)m * CDIM);
#pragma unroll
    for (int u = 0; u < 2; u++) {
        int c4 = tid + u*256;
        float4 g = g4[c4], bb = b4[c4], v = vals[u];
        float o0 = (v.x - mu) * rstd * g.x + bb.x;
        float o1 = (v.y - mu) * rstd * g.y + bb.y;
        float o2 = (v.z - mu) * rstd * g.z + bb.z;
        float o3 = (v.w - mu) * rstd * g.w + bb.w;
        __nv_bfloat16 h0 = __float2bfloat16(o0), h1 = __float2bfloat16(o1);
        __nv_bfloat16 h2 = __float2bfloat16(o2), h3 = __float2bfloat16(o3);
        __nv_bfloat162 hA; hA.x = h0; hA.y = h1;
        __nv_bfloat162 hB; hB.x = h2; hB.y = h3;
        __nv_bfloat162 lA; lA.x = __float2bfloat16(o0 - __bfloat162float(h0));
                           lA.y = __float2bfloat16(o1 - __bfloat162float(h1));
        __nv_bfloat162 lB; lB.x = __float2bfloat16(o2 - __bfloat162float(h2));
                           lB.y = __float2bfloat16(o3 - __bfloat162float(h3));
        yh2[2*c4]   = hA;  yh2[2*c4+1] = hB;
        yl2[2*c4]   = lA;  yl2[2*c4+1] = lB;
    }
}

/* ---------------- launch --------------------------------------------------- */
extern "C" void kernel_launch(void* const* d_in, const int* in_sizes, int n_in,
                              void* d_out, int out_size)
{
    const float* x_in     = (const float*)d_in[0];
    const float* shiftst  = (const float*)d_in[1];
    const float* wkvstate = (const float*)d_in[2];
    const float* tmr      = (const float*)d_in[3];
    const float* tmk      = (const float*)d_in[4];
    const float* tmv      = (const float*)d_in[5];
    const float* tmv2     = (const float*)d_in[6];
    const float* maa_w1   = (const float*)d_in[7];
    const float* maa_w2   = (const float*)d_in[8];
    const float* tmw      = (const float*)d_in[9];
    const float* ww1      = (const float*)d_in[10];
    const float* ww2      = (const float*)d_in[11];
    const float* tdecay   = (const float*)d_in[12];
    const float* dw1      = (const float*)d_in[13];
    const float* dw2      = (const float*)d_in[14];
    /* d_in[15] = time_faaaa: unused (u == 0 in this model) */
    const float* trec     = (const float*)d_in[16];
    const float* tkey     = (const float*)d_in[17];
    const float* value_w  = (const float*)d_in[18];
    const float* output_w = (const float*)d_in[19];
    const float* gamma    = (const float*)d_in[20];
    const float* beta     = (const float*)d_in[21];
    float* out = (float*)d_out;

    float *pX, *pXX1, *pMIX, *pXW1, *pMW, *pXW, *pT1, *pDEC, *pR, *pK, *pV, *pV2, *pY;
    __nv_bfloat16 *pXIH, *pXIL, *pYH, *pYL, *pVWH, *pVWL, *pOWH, *pOWL;
    cudaGetSymbolAddress((void**)&pX,   g_X);
    cudaGetSymbolAddress((void**)&pXX1, g_XX1);
    cudaGetSymbolAddress((void**)&pMIX, g_MIX);
    cudaGetSymbolAddress((void**)&pXW1, g_XW1);
    cudaGetSymbolAddress((void**)&pMW,  g_MW);
    cudaGetSymbolAddress((void**)&pXW,  g_XW);
    cudaGetSymbolAddress((void**)&pT1,  g_T1);
    cudaGetSymbolAddress((void**)&pDEC, g_DEC);
    cudaGetSymbolAddress((void**)&pR,   g_R);
    cudaGetSymbolAddress((void**)&pK,   g_K);
    cudaGetSymbolAddress((void**)&pV,   g_V);
    cudaGetSymbolAddress((void**)&pV2,  g_V2);
    cudaGetSymbolAddress((void**)&pY,   g_Y);
    cudaGetSymbolAddress((void**)&pXIH, g_XIH);
    cudaGetSymbolAddress((void**)&pXIL, g_XIL);
    cudaGetSymbolAddress((void**)&pYH,  g_YH);
    cudaGetSymbolAddress((void**)&pYL,  g_YL);
    cudaGetSymbolAddress((void**)&pVWH, g_VWH);
    cudaGetSymbolAddress((void**)&pVWL, g_VWL);
    cudaGetSymbolAddress((void**)&pOWH, g_OWH);
    cudaGetSymbolAddress((void**)&pOWL, g_OWL);

    const size_t SZ = (size_t)MTOT * CDIM;
    const int EW_BLOCKS = (int)(SZ / 4 / 256);
    const int SPLIT_BLK_X  = (int)(SZ / 4 / 256);
    const int SPLIT_BLK_W  = (int)((size_t)CDIM * CDIM / 4 / 256);

    /* bf16 hi/lo splits */
    split_kernel<<<SPLIT_BLK_X, 256>>>(x_in, pXIH, pXIL, (int)(SZ / 4));
    split_kernel<<<SPLIT_BLK_W, 256>>>(value_w,  pVWH, pVWL, (int)((size_t)CDIM*CDIM/4));
    split_kernel<<<SPLIT_BLK_W, 256>>>(output_w, pOWH, pOWL, (int)((size_t)CDIM*CDIM/4));

    /* X = x_in @ value_w^T  (wmma bf16x3) */
    gemm_wmma3<<<dim3(CDIM/128, MTOT/128), 256>>>(pXIH, pXIL, pVWH, pVWL, pX,
                                                  MTOT, CDIM, CDIM);

    /* XX1 = tanh(x_in @ maa_w1) */
    gemm_nn<<<dim3(1, MTOT/64), 256>>>(x_in, CDIM, 0, maa_w1, 128, pXX1, 128,
                                       MTOT, 128, CDIM, 1, (const float*)0);
    /* MIX[f] = XX1[:, f*32:(f+1)*32] @ maa_w2[f] */
    for (int f = 0; f < 4; f++)
        gemm_nn<<<dim3(CDIM/128, MTOT/64), 256>>>(pXX1, 128, f*32,
                                                  maa_w2 + (size_t)f*32*CDIM, CDIM,
                                                  pMIX + (size_t)f*SZ, CDIM,
                                                  MTOT, CDIM, 32, 0, (const float*)0);
    /* XW1 = tanh(X @ w_w1) */
    gemm_nn<<<dim3(1, MTOT/64), 256>>>(pX, CDIM, 0, ww1, 32, pXW1, 32,
                                       MTOT, 32, CDIM, 1, (const float*)0);
    /* MW = XW1 @ w_w2 */
    gemm_nn<<<dim3(CDIM/128, MTOT/64), 256>>>(pXW1, 32, 0, ww2, CDIM, pMW, CDIM,
                                              MTOT, CDIM, 32, 0, (const float*)0);
    /* XW = X + dxprev*(time_maa_w + MW) */
    ew_xw_kernel<<<EW_BLOCKS, 256>>>(pX, shiftst, pMW, tmw, pXW);
    /* T1 = tanh(XW @ decay_w1) */
    gemm_nn<<<dim3(1, MTOT/64), 256>>>(pXW, CDIM, 0, dw1, 128, pT1, 128,
                                       MTOT, 128, CDIM, 1, (const float*)0);
    /* DEC = exp(-exp(time_decay + T1 @ decay_w2)) */
    gemm_nn<<<dim3(CDIM/128, MTOT/64), 256>>>(pT1, 128, 0, dw2, CDIM, pDEC, CDIM,
                                              MTOT, CDIM, 128, 2, tdecay);
    /* r, k, v, v2 */
    ew_rkvv_kernel<<<EW_BLOCKS, 256>>>(pX, shiftst,
                                       pMIX, pMIX + SZ, pMIX + 2*SZ, pMIX + 3*SZ,
                                       pDEC, tmr, tmk, tmv, tmv2, trec, tkey,
                                       pR, pK, pV, pV2);
    /* WKV scan */
    wkv_kernel<<<BATCH*NH, 256>>>(pR, pK, pV, pDEC, wkvstate, pY);
    /* yn = LN(y + v2) -> bf16 hi/lo */
    ln_kernel<<<MTOT, 256>>>(pY, pV2, gamma, beta, pYH, pYL);
    /* out = yn @ output_w^T  (wmma bf16x3) */
    gemm_wmma3<<<dim3(CDIM/128, MTOT/128), 256>>>(pYH, pYL, pOWH, pOWL, out,
                                                  MTOT, CDIM, CDIM);
}

// round 10
// speedup vs baseline: 1.4970x; 1.0471x over previous
#include <cuda_runtime.h>
#include <cuda_bf16.h>
#include <mma.h>
#include <math.h>
#include <stdint.h>

using namespace nvcuda;

#define BATCH 4
#define TLEN  2048
#define CDIM  2048
#define HS    64
#define NH    32
#define MTOT  (BATCH*TLEN)   /* 8192 */

/* ---------------- scratch (static device allocations; no cudaMalloc) ------- */
__device__ float g_X  [(size_t)MTOT*CDIM];
__device__ float g_XX1[(size_t)MTOT*128];
__device__ float g_MIX[4][(size_t)MTOT*CDIM];
__device__ float g_XW1[(size_t)MTOT*32];
__device__ float g_MW [(size_t)MTOT*CDIM];
__device__ float g_XW [(size_t)MTOT*CDIM];
__device__ float g_T1 [(size_t)MTOT*128];
__device__ float g_DEC[(size_t)MTOT*CDIM];
__device__ float g_R  [(size_t)MTOT*CDIM];
__device__ float g_K  [(size_t)MTOT*CDIM];
__device__ float g_V  [(size_t)MTOT*CDIM];
__device__ float g_V2 [(size_t)MTOT*CDIM];
__device__ float g_Y  [(size_t)MTOT*CDIM];
/* bf16 hi/lo splits */
__device__ __nv_bfloat16 g_XIH[(size_t)MTOT*CDIM];
__device__ __nv_bfloat16 g_XIL[(size_t)MTOT*CDIM];
__device__ __nv_bfloat16 g_YH [(size_t)MTOT*CDIM];
__device__ __nv_bfloat16 g_YL [(size_t)MTOT*CDIM];
__device__ __nv_bfloat16 g_VWH[(size_t)CDIM*CDIM];
__device__ __nv_bfloat16 g_VWL[(size_t)CDIM*CDIM];
__device__ __nv_bfloat16 g_OWH[(size_t)CDIM*CDIM];
__device__ __nv_bfloat16 g_OWL[(size_t)CDIM*CDIM];

/* ================= bf16-split WMMA GEMM (NT), register-prefetch ============
   C[m,n] = sum_k A[m,k]*B[n,k],  A = AH+AL, B = BH+BL (bf16 hi/lo).
   Accumulate AH*BH + AH*BL + AL*BH in fp32 (lo*lo term dropped).
   Block 128x128, 8 warps (2 x 4), warp tile 64x32, K-chunk 32.
   Chunk c+1's global loads are issued into registers before the HMMA
   phase of chunk c, hiding DRAM latency under the 48 wmma ops.         */
#define WLD 40   /* smem row pitch in bf16 */

__global__ __launch_bounds__(256)
void gemm_wmma3(const __nv_bfloat16* __restrict__ AH, const __nv_bfloat16* __restrict__ AL,
                const __nv_bfloat16* __restrict__ BH, const __nv_bfloat16* __restrict__ BL,
                float* __restrict__ C, int M, int N, int K)
{
    __shared__ __nv_bfloat16 AsH[128][WLD];
    __shared__ __nv_bfloat16 AsL[128][WLD];
    __shared__ __nv_bfloat16 BsH[128][WLD];
    __shared__ __nv_bfloat16 BsL[128][WLD];

    const int tid = threadIdx.x;
    const int wid = tid >> 5;
    const int wm = wid & 1;        /* 0..1  -> 64-row slab  */
    const int wn = wid >> 1;       /* 0..3  -> 32-col slab  */
    const int bm = blockIdx.y * 128;
    const int bn = blockIdx.x * 128;

    wmma::fragment<wmma::accumulator, 16, 16, 16, float> acc[4][2];
#pragma unroll
    for (int i = 0; i < 4; i++)
#pragma unroll
        for (int j = 0; j < 2; j++) wmma::fill_fragment(acc[i][j], 0.f);

    /* loader mapping: i = tid + u*256 -> row = i>>2, col8 = (i&3)*8 */
    int lrow[2], lc8[2];
#pragma unroll
    for (int u = 0; u < 2; u++) {
        int i = tid + (u << 8);
        lrow[u] = i >> 2;
        lc8[u]  = (i & 3) << 3;
    }

    uint4 pAH[2], pAL[2], pBH[2], pBL[2];
#pragma unroll
    for (int u = 0; u < 2; u++) {
        size_t sa = (size_t)(bm + lrow[u]) * K + lc8[u];
        size_t sb = (size_t)(bn + lrow[u]) * K + lc8[u];
        pAH[u] = *(const uint4*)(AH + sa);
        pAL[u] = *(const uint4*)(AL + sa);
        pBH[u] = *(const uint4*)(BH + sb);
        pBL[u] = *(const uint4*)(BL + sb);
    }

    const int nchunks = K >> 5;
    for (int c = 0; c < nchunks; c++) {
        /* store prefetched chunk c to smem */
#pragma unroll
        for (int u = 0; u < 2; u++) {
            *(uint4*)&AsH[lrow[u]][lc8[u]] = pAH[u];
            *(uint4*)&AsL[lrow[u]][lc8[u]] = pAL[u];
            *(uint4*)&BsH[lrow[u]][lc8[u]] = pBH[u];
            *(uint4*)&BsL[lrow[u]][lc8[u]] = pBL[u];
        }
        __syncthreads();

        /* issue chunk c+1's loads; latency hides under the wmma phase */
        if (c + 1 < nchunks) {
            const int k0 = (c + 1) << 5;
#pragma unroll
            for (int u = 0; u < 2; u++) {
                size_t sa = (size_t)(bm + lrow[u]) * K + k0 + lc8[u];
                size_t sb = (size_t)(bn + lrow[u]) * K + k0 + lc8[u];
                pAH[u] = *(const uint4*)(AH + sa);
                pAL[u] = *(const uint4*)(AL + sa);
                pBH[u] = *(const uint4*)(BH + sb);
                pBL[u] = *(const uint4*)(BL + sb);
            }
        }

#pragma unroll
        for (int ks = 0; ks < 2; ks++) {
            wmma::fragment<wmma::matrix_b, 16, 16, 16, __nv_bfloat16, wmma::col_major> bh[2], bl[2];
#pragma unroll
            for (int j = 0; j < 2; j++) {
                wmma::load_matrix_sync(bh[j], &BsH[wn*32 + j*16][ks*16], WLD);
                wmma::load_matrix_sync(bl[j], &BsL[wn*32 + j*16][ks*16], WLD);
            }
#pragma unroll
            for (int i = 0; i < 4; i++) {
                wmma::fragment<wmma::matrix_a, 16, 16, 16, __nv_bfloat16, wmma::row_major> ah, al;
                wmma::load_matrix_sync(ah, &AsH[wm*64 + i*16][ks*16], WLD);
                wmma::load_matrix_sync(al, &AsL[wm*64 + i*16][ks*16], WLD);
#pragma unroll
                for (int j = 0; j < 2; j++) {
                    wmma::mma_sync(acc[i][j], ah, bh[j], acc[i][j]);
                    wmma::mma_sync(acc[i][j], ah, bl[j], acc[i][j]);
                    wmma::mma_sync(acc[i][j], al, bh[j], acc[i][j]);
                }
            }
        }
        __syncthreads();
    }

#pragma unroll
    for (int i = 0; i < 4; i++)
#pragma unroll
        for (int j = 0; j < 2; j++)
            wmma::store_matrix_sync(&C[(size_t)(bm + wm*64 + i*16) * N + bn + wn*32 + j*16],
                                    acc[i][j], N, wmma::mem_row_major);
}

/* ---------------- fp32 -> bf16 hi/lo split --------------------------------- */
__global__ void split_kernel(const float* __restrict__ in,
                             __nv_bfloat16* __restrict__ hi,
                             __nv_bfloat16* __restrict__ lo, int n4)
{
    int i = blockIdx.x * 256 + threadIdx.x;
    if (i >= n4) return;
    float4 x = ((const float4*)in)[i];
    __nv_bfloat16 h0 = __float2bfloat16(x.x), h1 = __float2bfloat16(x.y);
    __nv_bfloat16 h2 = __float2bfloat16(x.z), h3 = __float2bfloat16(x.w);
    __nv_bfloat162 hA; hA.x = h0; hA.y = h1;
    __nv_bfloat162 hB; hB.x = h2; hB.y = h3;
    __nv_bfloat162 lA; lA.x = __float2bfloat16(x.x - __bfloat162float(h0));
                       lA.y = __float2bfloat16(x.y - __bfloat162float(h1));
    __nv_bfloat162 lB; lB.x = __float2bfloat16(x.z - __bfloat162float(h2));
                       lB.y = __float2bfloat16(x.w - __bfloat162float(h3));
    ((__nv_bfloat162*)hi)[2*i]   = hA;
    ((__nv_bfloat162*)hi)[2*i+1] = hB;
    ((__nv_bfloat162*)lo)[2*i]   = lA;
    ((__nv_bfloat162*)lo)[2*i+1] = lB;
}

/* ---------------- generic NN GEMM: C[m,n] = f(sum_k A[m,lda..]*B[k,n]) ------ */
__global__ __launch_bounds__(256, 2)
void gemm_nn(const float* __restrict__ A, int lda, int aoff,
             const float* __restrict__ B, int ldb,
             float* __restrict__ C, int ldc,
             int M, int N, int K, int epi, const float* __restrict__ bias)
{
    __shared__ float As[64][36];
    __shared__ float Bs[32][128];
    const int tid = threadIdx.x;
    const int bm = blockIdx.y * 64;
    const int bn = blockIdx.x * 128;
    const int cx = tid & 31;
    const int rg = tid >> 5;

    float4 acc[8];
#pragma unroll
    for (int r = 0; r < 8; r++) acc[r] = make_float4(0.f,0.f,0.f,0.f);

    for (int k0 = 0; k0 < K; k0 += 32) {
#pragma unroll
        for (int u = 0; u < 2; u++) {
            int i = tid + 256*u;
            int r = i >> 3, kq = (i & 7) << 2;
            float4 v = *(const float4*)&A[(size_t)(bm + r) * lda + aoff + k0 + kq];
            *(float4*)&As[r][kq] = v;
        }
#pragma unroll
        for (int u = 0; u < 4; u++) {
            int i = tid + 256*u;
            int kr = i >> 5, nq = (i & 31) << 2;
            float4 v = make_float4(0.f,0.f,0.f,0.f);
            if (bn + nq < N)
                v = *(const float4*)&B[(size_t)(k0 + kr) * ldb + bn + nq];
            *(float4*)&Bs[kr][nq] = v;
        }
        __syncthreads();
#pragma unroll 8
        for (int k = 0; k < 32; k++) {
            float4 bv = *(const float4*)&Bs[k][cx << 2];
#pragma unroll
            for (int r = 0; r < 8; r++) {
                float a = As[rg*8 + r][k];
                acc[r].x = fmaf(a, bv.x, acc[r].x);
                acc[r].y = fmaf(a, bv.y, acc[r].y);
                acc[r].z = fmaf(a, bv.z, acc[r].z);
                acc[r].w = fmaf(a, bv.w, acc[r].w);
            }
        }
        __syncthreads();
    }
    const int n = bn + (cx << 2);
    if (n < N) {
#pragma unroll
        for (int r = 0; r < 8; r++) {
            float4 o = acc[r];
            if (epi == 1) {
                o.x = tanhf(o.x); o.y = tanhf(o.y); o.z = tanhf(o.z); o.w = tanhf(o.w);
            } else if (epi == 2) {
                o.x = expf(-expf(bias[n+0] + o.x));
                o.y = expf(-expf(bias[n+1] + o.y));
                o.z = expf(-expf(bias[n+2] + o.z));
                o.w = expf(-expf(bias[n+3] + o.w));
            }
            *(float4*)&C[(size_t)(bm + rg*8 + r) * ldc + n] = o;
        }
    }
}

/* ---------------- elementwise: XW = x + dxprev*(time_maa_w + mw) ----------- */
__global__ void ew_xw_kernel(const float* __restrict__ X, const float* __restrict__ shiftst,
                             const float* __restrict__ MW, const float* __restrict__ tmw,
                             float* __restrict__ XW)
{
    int i4 = blockIdx.x * 256 + threadIdx.x;
    int m = i4 >> 9, c4 = i4 & 511;
    int t = m & (TLEN-1), b = m >> 11;
    const float4* X4 = (const float4*)X;
    float4 x  = X4[i4];
    float4 xp = (t == 0) ? ((const float4*)shiftst)[(b << 9) + c4] : X4[i4 - 512];
    float4 mw = ((const float4*)MW)[i4];
    float4 w  = ((const float4*)tmw)[c4];
    float4 o;
    o.x = x.x + (xp.x - x.x) * (w.x + mw.x);
    o.y = x.y + (xp.y - x.y) * (w.y + mw.y);
    o.z = x.z + (xp.z - x.z) * (w.z + mw.z);
    o.w = x.w + (xp.w - x.w) * (w.w + mw.w);
    ((float4*)XW)[i4] = o;
}

/* ---------------- elementwise: r, k, v, v2 --------------------------------- */
__global__ void ew_rkvv_kernel(const float* __restrict__ X, const float* __restrict__ shiftst,
    const float* __restrict__ M0, const float* __restrict__ M1,
    const float* __restrict__ M2, const float* __restrict__ M3,
    const float* __restrict__ DEC,
    const float* __restrict__ tmr, const float* __restrict__ tmk,
    const float* __restrict__ tmv, const float* __restrict__ tmv2,
    const float* __restrict__ trec, const float* __restrict__ tkey,
    float* __restrict__ R, float* __restrict__ K,
    float* __restrict__ V, float* __restrict__ V2)
{
    int i4 = blockIdx.x * 256 + threadIdx.x;
    int m = i4 >> 9, c4 = i4 & 511;
    int t = m & (TLEN-1), b = m >> 11;
    const float4* X4 = (const float4*)X;
    float4 x  = X4[i4];
    float4 xp = (t == 0) ? ((const float4*)shiftst)[(b << 9) + c4] : X4[i4 - 512];
    float4 m0 = ((const float4*)M0)[i4];
    float4 m1 = ((const float4*)M1)[i4];
    float4 m2 = ((const float4*)M2)[i4];
    float4 m3 = ((const float4*)M3)[i4];
    float4 d  = ((const float4*)DEC)[i4];
    float4 cr = ((const float4*)tmr)[c4];
    float4 ck = ((const float4*)tmk)[c4];
    float4 cv = ((const float4*)tmv)[c4];
    float4 c2 = ((const float4*)tmv2)[c4];
    float4 rc = ((const float4*)trec)[c4];
    float4 kc = ((const float4*)tkey)[c4];
    float4 o_r, o_k, o_v, o_w;
#define RKVV_APPLY(f) do { \
    float dxv = xp.f - x.f; \
    o_r.f = (x.f + dxv*(cr.f + m0.f)) * rc.f; \
    o_k.f = (x.f + dxv*(ck.f + m1.f)) * kc.f * (1.f - d.f); \
    o_v.f =  x.f + dxv*(cv.f + m2.f); \
    o_w.f =  x.f + dxv*(c2.f + m3.f); \
} while(0)
    RKVV_APPLY(x); RKVV_APPLY(y); RKVV_APPLY(z); RKVV_APPLY(w);
#undef RKVV_APPLY
    ((float4*)R )[i4] = o_r;
    ((float4*)K )[i4] = o_k;
    ((float4*)V )[i4] = o_v;
    ((float4*)V2)[i4] = o_w;
}

/* ---------------- WKV sequential scan -------------------------------------- */
__global__ __launch_bounds__(256, 1)
void wkv_kernel(const float* __restrict__ Rp, const float* __restrict__ Kp,
                const float* __restrict__ Vp, const float* __restrict__ Dp,
                const float* __restrict__ S0, float* __restrict__ Y)
{
    const int bh = blockIdx.x;
    const int b = bh >> 5, h = bh & (NH-1);
    const int tid = threadIdx.x;
    const int j = tid >> 2, iq = tid & 3, i0 = iq << 4;

    float S[16];
    const float* s0p = S0 + (size_t)bh * HS * HS;
#pragma unroll
    for (int ii = 0; ii < 16; ii++) S[ii] = s0p[(i0 + ii) * HS + j];

    __shared__ float sbuf[2][4][64];

    const int grp = tid >> 6, lane = tid & 63;
    const size_t base = ((size_t)b * TLEN) * CDIM + h * HS;
    const float* myp =
        ((grp == 0) ? Rp : (grp == 1) ? Kp : (grp == 2) ? Dp : Vp) + base + lane;

    float pre[4];
#pragma unroll
    for (int u = 0; u < 4; u++) pre[u] = myp[(size_t)u * CDIM];

    const size_t ybase = base;
    for (int tc = 0; tc < TLEN; tc += 4) {
        float cur[4];
#pragma unroll
        for (int u = 0; u < 4; u++) cur[u] = pre[u];
        if (tc + 4 < TLEN) {
#pragma unroll
            for (int u = 0; u < 4; u++) pre[u] = myp[(size_t)(tc + 4 + u) * CDIM];
        }
#pragma unroll
        for (int u = 0; u < 4; u++) {
            const int t = tc + u;
            const int buf = t & 1;
            sbuf[buf][grp][lane] = cur[u];
            __syncthreads();
            const float4* r4 = (const float4*)sbuf[buf][0];
            const float4* k4 = (const float4*)sbuf[buf][1];
            const float4* d4 = (const float4*)sbuf[buf][2];
            const float vj = sbuf[buf][3][j];
            float y = 0.f;
#pragma unroll
            for (int q = 0; q < 4; q++) {
                float4 rv = r4[iq*4 + q];
                y = fmaf(rv.x, S[q*4+0], y);
                y = fmaf(rv.y, S[q*4+1], y);
                y = fmaf(rv.z, S[q*4+2], y);
                y = fmaf(rv.w, S[q*4+3], y);
            }
#pragma unroll
            for (int q = 0; q < 4; q++) {
                float4 dv = d4[iq*4 + q];
                float4 kv = k4[iq*4 + q];
                S[q*4+0] = fmaf(dv.x, S[q*4+0], kv.x * vj);
                S[q*4+1] = fmaf(dv.y, S[q*4+1], kv.y * vj);
                S[q*4+2] = fmaf(dv.z, S[q*4+2], kv.z * vj);
                S[q*4+3] = fmaf(dv.w, S[q*4+3], kv.w * vj);
            }
            y += __shfl_xor_sync(0xffffffffu, y, 1);
            y += __shfl_xor_sync(0xffffffffu, y, 2);
            if (iq == 0) Y[ybase + (size_t)t * CDIM + j] = y;
        }
    }
}

/* ---------------- fused add + LayerNorm -> bf16 hi/lo ---------------------- */
__global__ void ln_kernel(const float* __restrict__ Y, const float* __restrict__ V2,
                          const float* __restrict__ gamma, const float* __restrict__ beta,
                          __nv_bfloat16* __restrict__ YH, __nv_bfloat16* __restrict__ YL)
{
    const int m = blockIdx.x;
    const int tid = threadIdx.x;
    const float4* y4 = (const float4*)(Y  + (size_t)m * CDIM);
    const float4* v4 = (const float4*)(V2 + (size_t)m * CDIM);
    float4 vals[2];
    float s = 0.f, s2 = 0.f;
#pragma unroll
    for (int u = 0; u < 2; u++) {
        float4 a = y4[tid + u*256], b = v4[tid + u*256];
        float4 v = make_float4(a.x+b.x, a.y+b.y, a.z+b.z, a.w+b.w);
        vals[u] = v;
        s  += v.x + v.y + v.z + v.w;
        s2 += v.x*v.x + v.y*v.y + v.z*v.z + v.w*v.w;
    }
#pragma unroll
    for (int o = 16; o; o >>= 1) {
        s  += __shfl_xor_sync(0xffffffffu, s,  o);
        s2 += __shfl_xor_sync(0xffffffffu, s2, o);
    }
    __shared__ float sh[2][8];
    const int w = tid >> 5, l = tid & 31;
    if (l == 0) { sh[0][w] = s; sh[1][w] = s2; }
    __syncthreads();
    s = 0.f; s2 = 0.f;
#pragma unroll
    for (int i = 0; i < 8; i++) { s += sh[0][i]; s2 += sh[1][i]; }
    const float mu   = s  * (1.f / CDIM);
    const float var  = s2 * (1.f / CDIM) - mu * mu;
    const float rstd = rsqrtf(var + 1e-5f);
    const float4* g4 = (const float4*)gamma;
    const float4* b4 = (const float4*)beta;
    __nv_bfloat162* yh2 = (__nv_bfloat162*)(YH + (size_t)m * CDIM);
    __nv_bfloat162* yl2 = (__nv_bfloat162*)(YL + (size_t)m * CDIM);
#pragma unroll
    for (int u = 0; u < 2; u++) {
        int c4 = tid + u*256;
        float4 g = g4[c4], bb = b4[c4], v = vals[u];
        float o0 = (v.x - mu) * rstd * g.x + bb.x;
        float o1 = (v.y - mu) * rstd * g.y + bb.y;
        float o2 = (v.z - mu) * rstd * g.z + bb.z;
        float o3 = (v.w - mu) * rstd * g.w + bb.w;
        __nv_bfloat16 h0 = __float2bfloat16(o0), h1 = __float2bfloat16(o1);
        __nv_bfloat16 h2 = __float2bfloat16(o2), h3 = __float2bfloat16(o3);
        __nv_bfloat162 hA; hA.x = h0; hA.y = h1;
        __nv_bfloat162 hB; hB.x = h2; hB.y = h3;
        __nv_bfloat162 lA; lA.x = __float2bfloat16(o0 - __bfloat162float(h0));
                           lA.y = __float2bfloat16(o1 - __bfloat162float(h1));
        __nv_bfloat162 lB; lB.x = __float2bfloat16(o2 - __bfloat162float(h2));
                           lB.y = __float2bfloat16(o3 - __bfloat162float(h3));
        yh2[2*c4]   = hA;  yh2[2*c4+1] = hB;
        yl2[2*c4]   = lA;  yl2[2*c4+1] = lB;
    }
}

/* ---------------- launch --------------------------------------------------- */
extern "C" void kernel_launch(void* const* d_in, const int* in_sizes, int n_in,
                              void* d_out, int out_size)
{
    const float* x_in     = (const float*)d_in[0];
    const float* shiftst  = (const float*)d_in[1];
    const float* wkvstate = (const float*)d_in[2];
    const float* tmr      = (const float*)d_in[3];
    const float* tmk      = (const float*)d_in[4];
    const float* tmv      = (const float*)d_in[5];
    const float* tmv2     = (const float*)d_in[6];
    const float* maa_w1   = (const float*)d_in[7];
    const float* maa_w2   = (const float*)d_in[8];
    const float* tmw      = (const float*)d_in[9];
    const float* ww1      = (const float*)d_in[10];
    const float* ww2      = (const float*)d_in[11];
    const float* tdecay   = (const float*)d_in[12];
    const float* dw1      = (const float*)d_in[13];
    const float* dw2      = (const float*)d_in[14];
    /* d_in[15] = time_faaaa: unused (u == 0 in this model) */
    const float* trec     = (const float*)d_in[16];
    const float* tkey     = (const float*)d_in[17];
    const float* value_w  = (const float*)d_in[18];
    const float* output_w = (const float*)d_in[19];
    const float* gamma    = (const float*)d_in[20];
    const float* beta     = (const float*)d_in[21];
    float* out = (float*)d_out;

    float *pX, *pXX1, *pMIX, *pXW1, *pMW, *pXW, *pT1, *pDEC, *pR, *pK, *pV, *pV2, *pY;
    __nv_bfloat16 *pXIH, *pXIL, *pYH, *pYL, *pVWH, *pVWL, *pOWH, *pOWL;
    cudaGetSymbolAddress((void**)&pX,   g_X);
    cudaGetSymbolAddress((void**)&pXX1, g_XX1);
    cudaGetSymbolAddress((void**)&pMIX, g_MIX);
    cudaGetSymbolAddress((void**)&pXW1, g_XW1);
    cudaGetSymbolAddress((void**)&pMW,  g_MW);
    cudaGetSymbolAddress((void**)&pXW,  g_XW);
    cudaGetSymbolAddress((void**)&pT1,  g_T1);
    cudaGetSymbolAddress((void**)&pDEC, g_DEC);
    cudaGetSymbolAddress((void**)&pR,   g_R);
    cudaGetSymbolAddress((void**)&pK,   g_K);
    cudaGetSymbolAddress((void**)&pV,   g_V);
    cudaGetSymbolAddress((void**)&pV2,  g_V2);
    cudaGetSymbolAddress((void**)&pY,   g_Y);
    cudaGetSymbolAddress((void**)&pXIH, g_XIH);
    cudaGetSymbolAddress((void**)&pXIL, g_XIL);
    cudaGetSymbolAddress((void**)&pYH,  g_YH);
    cudaGetSymbolAddress((void**)&pYL,  g_YL);
    cudaGetSymbolAddress((void**)&pVWH, g_VWH);
    cudaGetSymbolAddress((void**)&pVWL, g_VWL);
    cudaGetSymbolAddress((void**)&pOWH, g_OWH);
    cudaGetSymbolAddress((void**)&pOWL, g_OWL);

    const size_t SZ = (size_t)MTOT * CDIM;
    const int EW_BLOCKS = (int)(SZ / 4 / 256);
    const int SPLIT_BLK_X  = (int)(SZ / 4 / 256);
    const int SPLIT_BLK_W  = (int)((size_t)CDIM * CDIM / 4 / 256);

    /* bf16 hi/lo splits */
    split_kernel<<<SPLIT_BLK_X, 256>>>(x_in, pXIH, pXIL, (int)(SZ / 4));
    split_kernel<<<SPLIT_BLK_W, 256>>>(value_w,  pVWH, pVWL, (int)((size_t)CDIM*CDIM/4));
    split_kernel<<<SPLIT_BLK_W, 256>>>(output_w, pOWH, pOWL, (int)((size_t)CDIM*CDIM/4));

    /* X = x_in @ value_w^T  (wmma bf16x3, register-prefetch pipelined) */
    gemm_wmma3<<<dim3(CDIM/128, MTOT/128), 256>>>(pXIH, pXIL, pVWH, pVWL, pX,
                                                  MTOT, CDIM, CDIM);

    /* XX1 = tanh(x_in @ maa_w1) */
    gemm_nn<<<dim3(1, MTOT/64), 256>>>(x_in, CDIM, 0, maa_w1, 128, pXX1, 128,
                                       MTOT, 128, CDIM, 1, (const float*)0);
    /* MIX[f] = XX1[:, f*32:(f+1)*32] @ maa_w2[f] */
    for (int f = 0; f < 4; f++)
        gemm_nn<<<dim3(CDIM/128, MTOT/64), 256>>>(pXX1, 128, f*32,
                                                  maa_w2 + (size_t)f*32*CDIM, CDIM,
                                                  pMIX + (size_t)f*SZ, CDIM,
                                                  MTOT, CDIM, 32, 0, (const float*)0);
    /* XW1 = tanh(X @ w_w1) */
    gemm_nn<<<dim3(1, MTOT/64), 256>>>(pX, CDIM, 0, ww1, 32, pXW1, 32,
                                       MTOT, 32, CDIM, 1, (const float*)0);
    /* MW = XW1 @ w_w2 */
    gemm_nn<<<dim3(CDIM/128, MTOT/64), 256>>>(pXW1, 32, 0, ww2, CDIM, pMW, CDIM,
                                              MTOT, CDIM, 32, 0, (const float*)0);
    /* XW = X + dxprev*(time_maa_w + MW) */
    ew_xw_kernel<<<EW_BLOCKS, 256>>>(pX, shiftst, pMW, tmw, pXW);
    /* T1 = tanh(XW @ decay_w1) */
    gemm_nn<<<dim3(1, MTOT/64), 256>>>(pXW, CDIM, 0, dw1, 128, pT1, 128,
                                       MTOT, 128, CDIM, 1, (const float*)0);
    /* DEC = exp(-exp(time_decay + T1 @ decay_w2)) */
    gemm_nn<<<dim3(CDIM/128, MTOT/64), 256>>>(pT1, 128, 0, dw2, CDIM, pDEC, CDIM,
                                              MTOT, CDIM, 128, 2, tdecay);
    /* r, k, v, v2 */
    ew_rkvv_kernel<<<EW_BLOCKS, 256>>>(pX, shiftst,
                                       pMIX, pMIX + SZ, pMIX + 2*SZ, pMIX + 3*SZ,
                                       pDEC, tmr, tmk, tmv, tmv2, trec, tkey,
                                       pR, pK, pV, pV2);
    /* WKV scan */
    wkv_kernel<<<BATCH*NH, 256>>>(pR, pK, pV, pDEC, wkvstate, pY);
    /* yn = LN(y + v2) -> bf16 hi/lo */
    ln_kernel<<<MTOT, 256>>>(pY, pV2, gamma, beta, pYH, pYL);
    /* out = yn @ output_w^T  (wmma bf16x3, register-prefetch pipelined) */
    gemm_wmma3<<<dim3(CDIM/128, MTOT/128), 256>>>(pYH, pYL, pOWH, pOWL, out,
                                                  MTOT, CDIM, CDIM);
}